// round 1
// baseline (speedup 1.0000x reference)
#include <cuda_runtime.h>
#include <math.h>

#define H 64
#define NN 12000
#define NE 50000
#define EHD 128          // 2H
#define QC 8192          // H * 2H  (columns of q)

// ---------------- scratch (device globals; allocation-free) ----------------
__device__ float g_eh[NE * EHD];          // 25.6 MB  relu(edge@W1.T+b1)
__device__ float g_q[NN * QC];            // 393 MB   q[n, k*128+c]
__device__ float g_agg[NN * H];           // 3 MB     scatter-sum target
__device__ float g_WihT[64 * 192];        // transposed GRU weights
__device__ float g_WhhT[64 * 192];
__device__ int   g_cnt[NN];
__device__ int   g_off[NN + 1];
__device__ int   g_cur[NN];
__device__ int   g_elist[NE];

// ---------------- 0: zero agg + counts ----------------
__global__ void zero_kernel() {
    int i = blockIdx.x * blockDim.x + threadIdx.x;
    int stride = gridDim.x * blockDim.x;
    for (int j = i; j < NN * H; j += stride) g_agg[j] = 0.f;
    for (int j = i; j < NN; j += stride) g_cnt[j] = 0;
}

// ---------------- 1: eh = relu(edge @ W1.T + b1) ----------------
__global__ __launch_bounds__(128) void eh_kernel(const float* __restrict__ edge,
                                                 const float* __restrict__ W1,
                                                 const float* __restrict__ b1) {
    __shared__ float W1t[64 * 129];   // [h][c], stride 129 -> conflict-free both ways
    __shared__ float e_s[64];
    int t = threadIdx.x;
    for (int i = t; i < EHD * H; i += 128) {
        int c = i >> 6, h = i & 63;
        W1t[h * 129 + c] = W1[i];
    }
    float bias = b1[t];
    __syncthreads();
    for (int e = blockIdx.x; e < NE; e += gridDim.x) {
        __syncthreads();
        if (t < 64) e_s[t] = edge[(size_t)e * 64 + t];
        __syncthreads();
        float acc = bias;
#pragma unroll 16
        for (int h = 0; h < 64; h++) acc = fmaf(e_s[h], W1t[h * 129 + t], acc);
        g_eh[(size_t)e * EHD + t] = fmaxf(acc, 0.f);
    }
}

// ---------------- 2: q[n, j] = sum_h node[n,h] * W2flat[h*8192 + j] ----------
// GEMM M=12000, N=8192, K=64. CTA tile 128x128, full K resident for A,
// B streamed in two K=32 chunks (static smem = 48KB exactly).
__global__ __launch_bounds__(256, 2) void q_gemm(const float* __restrict__ node,
                                                 const float* __restrict__ W2) {
    __shared__ float As[64 * 128];   // [k][m]
    __shared__ float Bs[32 * 128];   // [k][n]
    int m0 = blockIdx.y * 128, n0 = blockIdx.x * 128;
    int tid = threadIdx.x;

    // load A tile (transposed to k-major); 128 rows x 16 float4
    for (int i = tid; i < 2048; i += 256) {
        int r = i >> 4, c4 = i & 15;
        float4 v = make_float4(0.f, 0.f, 0.f, 0.f);
        int m = m0 + r;
        if (m < NN) v = reinterpret_cast<const float4*>(node)[m * 16 + c4];
        As[(c4 * 4 + 0) * 128 + r] = v.x;
        As[(c4 * 4 + 1) * 128 + r] = v.y;
        As[(c4 * 4 + 2) * 128 + r] = v.z;
        As[(c4 * 4 + 3) * 128 + r] = v.w;
    }

    int tx = tid & 15, ty = tid >> 4;
    int mr = ty * 8, nc = tx * 8;
    float acc[8][8];
#pragma unroll
    for (int i = 0; i < 8; i++)
#pragma unroll
        for (int j = 0; j < 8; j++) acc[i][j] = 0.f;

    for (int kb = 0; kb < 64; kb += 32) {
        __syncthreads();
        // load B chunk: rows kb..kb+31, cols n0..n0+127
        for (int i = tid; i < 1024; i += 256) {
            int r = i >> 5, c4 = i & 31;
            reinterpret_cast<float4*>(Bs)[r * 32 + c4] =
                reinterpret_cast<const float4*>(W2)[(kb + r) * 2048 + (n0 >> 2) + c4];
        }
        __syncthreads();
#pragma unroll 8
        for (int k = 0; k < 32; k++) {
            float a[8], b[8];
            *(float4*)&a[0] = *(float4*)&As[(kb + k) * 128 + mr];
            *(float4*)&a[4] = *(float4*)&As[(kb + k) * 128 + mr + 4];
            *(float4*)&b[0] = *(float4*)&Bs[k * 128 + nc];
            *(float4*)&b[4] = *(float4*)&Bs[k * 128 + nc + 4];
#pragma unroll
            for (int i = 0; i < 8; i++)
#pragma unroll
                for (int j = 0; j < 8; j++) acc[i][j] = fmaf(a[i], b[j], acc[i][j]);
        }
    }

#pragma unroll
    for (int i = 0; i < 8; i++) {
        int m = m0 + mr + i;
        if (m < NN) {
            float* dst = g_q + (size_t)m * QC + n0 + nc;
            *(float4*)dst = *(float4*)&acc[i][0];
            *(float4*)(dst + 4) = *(float4*)&acc[i][4];
        }
    }
}

// ---------------- 3: CSR by src ----------------
__global__ void count_kernel(const int* __restrict__ src) {
    int e = blockIdx.x * blockDim.x + threadIdx.x;
    if (e < NE) atomicAdd(&g_cnt[src[e]], 1);
}

__global__ void scan_kernel() {
    __shared__ int sm[1024];
    int tid = threadIdx.x;
    const int C = 12;   // 1024*12 = 12288 >= NN
    int base = tid * C;
    int loc[C];
    int s = 0;
#pragma unroll
    for (int i = 0; i < C; i++) {
        int v = (base + i < NN) ? g_cnt[base + i] : 0;
        loc[i] = s;
        s += v;
    }
    sm[tid] = s;
    __syncthreads();
    for (int d = 1; d < 1024; d <<= 1) {
        int v = (tid >= d) ? sm[tid - d] : 0;
        __syncthreads();
        if (tid >= d) sm[tid] += v;
        __syncthreads();
    }
    int ex = sm[tid] - s;
#pragma unroll
    for (int i = 0; i < C; i++) {
        if (base + i < NN) {
            g_off[base + i] = ex + loc[i];
            g_cur[base + i] = ex + loc[i];
        }
    }
    if (tid == 1023) g_off[NN] = sm[1023];
}

__global__ void scatter_kernel(const int* __restrict__ src) {
    int e = blockIdx.x * blockDim.x + threadIdx.x;
    if (e < NE) {
        int p = atomicAdd(&g_cur[src[e]], 1);
        g_elist[p] = e;
    }
}

// ---------------- 4: per-src-node message + scatter-add ----------------
// msg[e,k] = sum_c eh[e,c]*q[src, k*128+c] + sum_h x[h]*b2[h*64+k]
__global__ __launch_bounds__(128) void msg_kernel(const float* __restrict__ node,
                                                  const float* __restrict__ b2,
                                                  const int* __restrict__ dst) {
    __shared__ float q_s[128 * 65];   // [c][k], stride 65 -> conflict-free
    __shared__ float eh_s[128];
    __shared__ float x_s[64];
    __shared__ float bb_s[64];
    __shared__ float part_s[128];
    int n = blockIdx.x;
    int t = threadIdx.x;

    int beg = g_off[n], end = g_off[n + 1];
    if (beg == end) return;   // uniform exit, no barriers crossed

    const float* qn = g_q + (size_t)n * QC;
    for (int j = t; j < QC; j += 128) {
        int k = j >> 7, c = j & 127;
        q_s[c * 65 + k] = qn[j];
    }
    if (t < 64) x_s[t] = node[n * 64 + t];
    __syncthreads();
    if (t < 64) {
        float bb = 0.f;
#pragma unroll 8
        for (int h = 0; h < 64; h++) bb = fmaf(x_s[h], b2[h * 64 + t], bb);
        bb_s[t] = bb;
    }

    int k = t & 63, half = t >> 6;
    const float* qp = q_s + (half * 64) * 65 + k;
    for (int ei = beg; ei < end; ei++) {
        int e = g_elist[ei];
        __syncthreads();
        eh_s[t] = g_eh[(size_t)e * EHD + t];
        __syncthreads();
        float acc = 0.f;
#pragma unroll 16
        for (int c = 0; c < 64; c++) acc = fmaf(eh_s[half * 64 + c], qp[c * 65], acc);
        part_s[t] = acc;
        __syncthreads();
        if (t < 64) {
            float m = part_s[t] + part_s[t + 64] + bb_s[t];
            atomicAdd(&g_agg[dst[e] * 64 + t], m);
        }
    }
}

// ---------------- 5a: transpose GRU weights ----------------
__global__ void wt_kernel(const float* __restrict__ Wih, const float* __restrict__ Whh) {
    int i = blockIdx.x * blockDim.x + threadIdx.x;
    if (i < 192 * 64) {
        int j = i >> 6, h = i & 63;
        g_WihT[h * 192 + j] = Wih[i];
        g_WhhT[h * 192 + j] = Whh[i];
    }
}

// ---------------- 5: relu(agg) -> GRU -> LayerNorm ----------------
__global__ __launch_bounds__(256) void gru_ln_kernel(const float* __restrict__ hidden,
                                                     const float* __restrict__ bih,
                                                     const float* __restrict__ bhh,
                                                     const float* __restrict__ gamma,
                                                     const float* __restrict__ beta,
                                                     float* __restrict__ out) {
    __shared__ float xs[4][64], hs[4][64];
    __shared__ float redA[8], redB[8];
    int t = threadIdx.x;
    int sub = t >> 6, k = t & 63;
    int wid = t >> 5, lane = t & 31;
    float bi0 = bih[k], bi1 = bih[64 + k], bi2 = bih[128 + k];
    float bh0 = bhh[k], bh1 = bhh[64 + k], bh2 = bhh[128 + k];
    float gm = gamma[k], bt = beta[k];

    for (int n0 = blockIdx.x * 4; n0 < NN; n0 += gridDim.x * 4) {
        int n = n0 + sub;   // NN % 4 == 0 -> always valid
        float x = fmaxf(g_agg[n * 64 + k], 0.f);
        float hv = hidden[n * 64 + k];
        xs[sub][k] = x;
        hs[sub][k] = hv;
        __syncthreads();
        float gi0 = bi0, gi1 = bi1, gi2 = bi2;
        float gh0 = bh0, gh1 = bh1, gh2 = bh2;
#pragma unroll 8
        for (int h = 0; h < 64; h++) {
            float xv = xs[sub][h], hh = hs[sub][h];
            const float* wi = &g_WihT[h * 192];
            const float* wh = &g_WhhT[h * 192];
            gi0 = fmaf(xv, wi[k], gi0);
            gi1 = fmaf(xv, wi[64 + k], gi1);
            gi2 = fmaf(xv, wi[128 + k], gi2);
            gh0 = fmaf(hh, wh[k], gh0);
            gh1 = fmaf(hh, wh[64 + k], gh1);
            gh2 = fmaf(hh, wh[128 + k], gh2);
        }
        float r = 1.f / (1.f + expf(-(gi0 + gh0)));
        float z = 1.f / (1.f + expf(-(gi1 + gh1)));
        float nn2 = tanhf(gi2 + r * gh2);
        float o = (1.f - z) * nn2 + z * hv;

        float s1 = o, s2 = o * o;
#pragma unroll
        for (int d = 16; d > 0; d >>= 1) {
            s1 += __shfl_xor_sync(0xffffffffu, s1, d);
            s2 += __shfl_xor_sync(0xffffffffu, s2, d);
        }
        if (lane == 0) { redA[wid] = s1; redB[wid] = s2; }
        __syncthreads();
        float S1 = redA[sub * 2] + redA[sub * 2 + 1];
        float S2 = redB[sub * 2] + redB[sub * 2 + 1];
        float mu = S1 * 0.015625f;
        float var = S2 * 0.015625f - mu * mu;
        out[n * 64 + k] = (o - mu) * rsqrtf(var + 1e-5f) * gm + bt;
        __syncthreads();
    }
}

// ---------------- launch ----------------
extern "C" void kernel_launch(void* const* d_in, const int* in_sizes, int n_in,
                              void* d_out, int out_size) {
    const float* node   = (const float*)d_in[0];
    const float* edge   = (const float*)d_in[1];
    const float* hidden = (const float*)d_in[2];
    const int*   src    = (const int*)d_in[3];
    const int*   dst    = (const int*)d_in[4];
    const float* W1     = (const float*)d_in[5];
    const float* b1     = (const float*)d_in[6];
    const float* W2     = (const float*)d_in[7];
    const float* b2     = (const float*)d_in[8];
    const float* Wih    = (const float*)d_in[9];
    const float* Whh    = (const float*)d_in[10];
    const float* bih    = (const float*)d_in[11];
    const float* bhh    = (const float*)d_in[12];
    const float* gamma  = (const float*)d_in[13];
    const float* beta   = (const float*)d_in[14];
    float* out = (float*)d_out;

    zero_kernel<<<1024, 256>>>();
    wt_kernel<<<(192 * 64 + 255) / 256, 256>>>(Wih, Whh);
    eh_kernel<<<2048, 128>>>(edge, W1, b1);
    q_gemm<<<dim3(QC / 128, (NN + 127) / 128), 256>>>(node, W2);
    count_kernel<<<(NE + 255) / 256, 256>>>(src);
    scan_kernel<<<1, 1024>>>();
    scatter_kernel<<<(NE + 255) / 256, 256>>>(src);
    msg_kernel<<<NN, 128>>>(node, b2, dst);
    gru_ln_kernel<<<296, 256>>>(hidden, bih, bhh, gamma, beta, out);
}